// round 9
// baseline (speedup 1.0000x reference)
#include <cuda_runtime.h>
#include <cuda_bf16.h>
#include <math.h>
#include <stdint.h>

#define T_TOK 64
#define S_SP  729
#define H_DIM 1152
#define E_DIM 512
#define NE    9
#define NL    4
#define B_IMG 8
#define P_PAT 8

#define OUT_MAJOR 0
#define OUT_FINAL (T_TOK * 4 * H_DIM)
#define OUT_PREDS (OUT_FINAL + B_IMG * H_DIM)

__device__ float g_poolpart[B_IMG * 9 * H_DIM];
__device__ float g_puv    [NL * 17 * E_DIM];
__device__ float g_prompts[NL * B_IMG * NE * E_DIM];
__device__ float g_scores [(size_t)NL * T_TOK * NE * S_SP];
__device__ float g_meanatt[T_TOK * NE * S_SP];
__device__ float g_pes    [T_TOK * NE];
__device__ float g_gsig   [T_TOK * 4];
__device__ __align__(16) __nv_bfloat16 g_Whi[(size_t)NL * E_DIM * H_DIM];
__device__ __align__(16) __nv_bfloat16 g_Wlo[(size_t)NL * E_DIM * H_DIM];

__device__ __forceinline__ uint32_t smem_u32(const void* p) {
    uint32_t a;
    asm("{ .reg .u64 t; cvta.to.shared.u64 t, %1; cvt.u32.u64 %0, t; }" : "=r"(a) : "l"(p));
    return a;
}
__device__ __forceinline__ void cpasync16(uint32_t dst, const void* src) {
    asm volatile("cp.async.cg.shared.global [%0], [%1], 16;" :: "r"(dst), "l"(src));
}
#define CP_COMMIT() asm volatile("cp.async.commit_group;" ::: "memory")
#define CP_WAIT1()  asm volatile("cp.async.wait_group 1;" ::: "memory")

__device__ __forceinline__ float blockSum256(float v) {
    __shared__ float red[8];
    int lane = threadIdx.x & 31, wid = threadIdx.x >> 5;
    #pragma unroll
    for (int o = 16; o; o >>= 1) v += __shfl_xor_sync(0xffffffffu, v, o);
    if (lane == 0) red[wid] = v;
    __syncthreads();
    if (wid == 0) {
        float r = (lane < 8) ? red[lane] : 0.f;
        #pragma unroll
        for (int o = 4; o; o >>= 1) r += __shfl_xor_sync(0xffffffffu, r, o);
        if (lane == 0) red[0] = r;
    }
    __syncthreads();
    float r = red[0];
    __syncthreads();
    return r;
}
__device__ __forceinline__ float blockMax256(float v) {
    __shared__ float red[8];
    int lane = threadIdx.x & 31, wid = threadIdx.x >> 5;
    #pragma unroll
    for (int o = 16; o; o >>= 1) v = fmaxf(v, __shfl_xor_sync(0xffffffffu, v, o));
    if (lane == 0) red[wid] = v;
    __syncthreads();
    if (wid == 0) {
        float r = (lane < 8) ? red[lane] : -INFINITY;
        #pragma unroll
        for (int o = 4; o; o >>= 1) r = fmaxf(r, __shfl_xor_sync(0xffffffffu, r, o));
        if (lane == 0) red[0] = r;
    }
    __syncthreads();
    float r = red[0];
    __syncthreads();
    return r;
}
__device__ __forceinline__ float gelu_exact(float x) {
    return 0.5f * x * (1.0f + erff(x * 0.7071067811865475f));
}
__device__ __forceinline__ uint32_t pk2(__nv_bfloat16 a, __nv_bfloat16 b) {
    return ((uint32_t)__bfloat16_as_ushort(b) << 16) | (uint32_t)__bfloat16_as_ushort(a);
}
__device__ __forceinline__ void mma16816(float* d, const uint32_t* a, uint32_t b0, uint32_t b1) {
    asm volatile(
        "mma.sync.aligned.m16n8k16.row.col.f32.bf16.bf16.f32 "
        "{%0,%1,%2,%3}, {%4,%5,%6,%7}, {%8,%9}, {%0,%1,%2,%3};"
        : "+f"(d[0]), "+f"(d[1]), "+f"(d[2]), "+f"(d[3])
        : "r"(a[0]), "r"(a[1]), "r"(a[2]), "r"(a[3]), "r"(b0), "r"(b1));
}

// launch 0: W split
__global__ void k_wsplit(const float* __restrict__ sw) {
    const size_t N = (size_t)NL * E_DIM * H_DIM;
    for (size_t i = (size_t)blockIdx.x * 256 + threadIdx.x; i < N; i += (size_t)gridDim.x * 256) {
        float w = sw[i];
        __nv_bfloat16 h = __float2bfloat16(w);
        g_Whi[i] = h;
        g_Wlo[i] = __float2bfloat16(w - __bfloat162float(h));
    }
}

// launch 1: pooled partials, grid (8,9), block 128
__global__ void k_pre1(const float* __restrict__ ov, const float* __restrict__ pw) {
    int b = blockIdx.x, sc = blockIdx.y, tid = threadIdx.x;
    float acc[9];
    #pragma unroll
    for (int j = 0; j < 9; j++) acc[j] = 0.f;
    const float* base = ov + (size_t)(b * P_PAT) * S_SP * H_DIM + (size_t)sc * 81 * H_DIM + tid;
    for (int s = 0; s < 81; s++) {
        float w = pw[sc * 81 + s];
        const float* p = base + (size_t)s * H_DIM;
        #pragma unroll
        for (int j = 0; j < 9; j++) acc[j] += w * p[j * 128];
    }
    #pragma unroll
    for (int j = 0; j < 9; j++)
        g_poolpart[((size_t)b * 9 + sc) * H_DIM + tid + j * 128] = acc[j];
}

// launch 2: fused cls1 + cls2 + puv + prompt-normalize, ONE block of 512
__global__ void __launch_bounds__(512, 1)
k_pre2(const float* __restrict__ w1, const float* __restrict__ b1,
       const float* __restrict__ pb,
       const float* __restrict__ w2, const float* __restrict__ b2,
       const float* __restrict__ emo, const float* __restrict__ pw,
       const float* __restrict__ prm_b) {
    extern __shared__ float P[];
    float* pooled = P;               // 8*1152 = 9216
    float* hidden = P + 9216;        // 8*512  = 4096
    float* clsS   = P + 13312;       // 8*512  = 4096
    float* es     = P + 17408;       // 9*512  = 4608
    int tid = threadIdx.x, wid = tid >> 5, lane = tid & 31;

    float pbias = pb[0];
    for (int idx = tid; idx < B_IMG * H_DIM; idx += 512) {
        int b = idx / H_DIM, h = idx - b * H_DIM;
        float s = pbias;
        #pragma unroll
        for (int sc = 0; sc < 9; sc++) s += g_poolpart[((size_t)b * 9 + sc) * H_DIM + h];
        pooled[idx] = s;
    }
    for (int idx = tid; idx < NE * E_DIM; idx += 512) es[idx] = emo[idx];
    __syncthreads();

    // cls1: hidden = gelu(pooled @ w1^T + b1), 16 warps x 32 o's
    for (int o = wid; o < E_DIM; o += 16) {
        float acc[8];
        #pragma unroll
        for (int b = 0; b < 8; b++) acc[b] = 0.f;
        const float* wr = w1 + (size_t)o * H_DIM;
        for (int k = lane; k < H_DIM; k += 32) {
            float w = wr[k];
            #pragma unroll
            for (int b = 0; b < 8; b++) acc[b] += w * pooled[b * H_DIM + k];
        }
        #pragma unroll
        for (int b = 0; b < 8; b++)
            #pragma unroll
            for (int off = 16; off; off >>= 1) acc[b] += __shfl_xor_sync(0xffffffffu, acc[b], off);
        if (lane == 0) {
            float bv = b1[o];
            #pragma unroll
            for (int b = 0; b < 8; b++) hidden[b * E_DIM + o] = gelu_exact(acc[b] + bv);
        }
    }
    __syncthreads();

    // cls2
    for (int o = wid; o < E_DIM; o += 16) {
        float acc[8];
        #pragma unroll
        for (int b = 0; b < 8; b++) acc[b] = 0.f;
        const float* wr = w2 + (size_t)o * E_DIM;
        for (int k = lane; k < E_DIM; k += 32) {
            float w = wr[k];
            #pragma unroll
            for (int b = 0; b < 8; b++) acc[b] += w * hidden[b * E_DIM + k];
        }
        #pragma unroll
        for (int b = 0; b < 8; b++)
            #pragma unroll
            for (int off = 16; off; off >>= 1) acc[b] += __shfl_xor_sync(0xffffffffu, acc[b], off);
        if (lane == 0) {
            float bv = b2[o];
            #pragma unroll
            for (int b = 0; b < 8; b++) clsS[b * E_DIM + o] = acc[b] + bv;
        }
    }
    __syncthreads();

    // puv: u[i,n,o], v[i,b,o] -> g_puv
    for (int i = 0; i < NL; i++) {
        for (int o = wid; o < E_DIM; o += 16) {
            const float* wr = pw + ((size_t)i * E_DIM + o) * 1024;
            float acc[17];
            #pragma unroll
            for (int j = 0; j < 17; j++) acc[j] = 0.f;
            for (int c = lane; c < 512; c += 32) {
                float a = wr[c];
                #pragma unroll
                for (int n = 0; n < NE; n++) acc[n] += a * es[n * 512 + c];
                float bb = wr[512 + c];
                #pragma unroll
                for (int b = 0; b < B_IMG; b++) acc[9 + b] += bb * clsS[b * 512 + c];
            }
            #pragma unroll
            for (int j = 0; j < 17; j++)
                #pragma unroll
                for (int off = 16; off; off >>= 1) acc[j] += __shfl_xor_sync(0xffffffffu, acc[j], off);
            if (lane == 0) {
                #pragma unroll
                for (int j = 0; j < 17; j++) g_puv[((size_t)i * 17 + j) * 512 + o] = acc[j];
            }
        }
    }
    __syncthreads();

    // normalize -> g_prompts: 288 rows, one warp per row
    for (int r = wid; r < NL * B_IMG * NE; r += 16) {
        int i = r / 72, rem = r % 72, b = rem / 9, n = rem % 9;
        float vals[16];
        float nsq = 0.f;
        #pragma unroll
        for (int j = 0; j < 16; j++) {
            int o = lane + j * 32;
            float x = g_puv[((size_t)i * 17 + n) * 512 + o]
                    + g_puv[((size_t)i * 17 + 9 + b) * 512 + o]
                    + prm_b[i * 512 + o];
            vals[j] = x;
            nsq += x * x;
        }
        #pragma unroll
        for (int off = 16; off; off >>= 1) nsq += __shfl_xor_sync(0xffffffffu, nsq, off);
        float inv = rsqrtf(nsq);
        size_t base = ((size_t)(i * B_IMG + b) * NE + n) * E_DIM;
        #pragma unroll
        for (int j = 0; j < 16; j++) g_prompts[base + lane + j * 32] = vals[j] * inv;
    }
}

// ======= launch 3 (ncu-captured): pipelined sig GEMM, block 512 =======
#define NCH 36
#define SMM_PSM   0
#define SMM_SBI   18432
#define SMM_RED   20480
#define SMM_A     23040
#define SMM_W     43520
#define SMM_YSM   43520
#define SMM_TOTAL 207360
#define Y_STR 260

__global__ void __launch_bounds__(512, 1)
k_sig_mma(const float* __restrict__ sig, const float* __restrict__ sb) {
    extern __shared__ char smem[];
    uint32_t sbase = smem_u32(smem);
    float* Psm = reinterpret_cast<float*>(smem + SMM_PSM);
    float* Sbi = reinterpret_cast<float*>(smem + SMM_SBI);
    float* red = reinterpret_cast<float*>(smem + SMM_RED);
    float* ysm = reinterpret_cast<float*>(smem + SMM_YSM);

    int tid = threadIdx.x, wid = tid >> 5, lane = tid & 31;
    int wm = wid >> 3, wn = wid & 7;
    int g = lane >> 2, tig = lane & 3;
    int s0 = blockIdx.x * 64;
    int t = blockIdx.y, i = blockIdx.z, b = t >> 3;

    {
        size_t pbase = ((size_t)(i * B_IMG + b) * NE) * E_DIM;
        for (int idx = tid; idx < NE * E_DIM; idx += 512) Psm[idx] = g_prompts[pbase + idx];
        for (int idx = tid; idx < E_DIM; idx += 512) Sbi[idx] = sb[i * E_DIM + idx];
        for (int idx = tid; idx < 640; idx += 512) red[idx] = 0.f;
    }

    const float* Xbase = sig + ((size_t)(i * T_TOK + t) * S_SP) * H_DIM;
    const char* WH = reinterpret_cast<const char*>(g_Whi) + (size_t)i * E_DIM * H_DIM * 2;
    const char* WL = reinterpret_cast<const char*>(g_Wlo) + (size_t)i * E_DIM * H_DIM * 2;

    float acc[2][8][4];
    #pragma unroll
    for (int mt = 0; mt < 2; mt++)
        #pragma unroll
        for (int nt = 0; nt < 8; nt++)
            #pragma unroll
            for (int c = 0; c < 4; c++) acc[mt][nt][c] = 0.f;

    int xrow = tid >> 2, xkc = tid & 3;
    int xs = s0 + xrow;
    const float* xptr = (tid < 256 && xs < S_SP) ? (Xbase + (size_t)xs * H_DIM + xkc * 8) : nullptr;
    float xv[8];

#define ISSUE_W(CH, BUF) do { \
    uint32_t wHi = sbase + SMM_W + (BUF) * 81920; \
    int n_ = tid; \
    const char* sH = WH + ((size_t)n_ * H_DIM + (CH) * 32) * 2; \
    const char* sL = WL + ((size_t)n_ * H_DIM + (CH) * 32) * 2; \
    uint32_t dH = wHi + n_ * 80; \
    uint32_t dL = dH + 40960; \
    cpasync16(dH, sH); cpasync16(dH + 16, sH + 16); \
    cpasync16(dH + 32, sH + 32); cpasync16(dH + 48, sH + 48); \
    cpasync16(dL, sL); cpasync16(dL + 16, sL + 16); \
    cpasync16(dL + 32, sL + 32); cpasync16(dL + 48, sL + 48); \
} while (0)

#define LOAD_X(CH) do { \
    if (xptr) { \
        const float* p_ = xptr + (CH) * 32; \
        float4 f0_ = *reinterpret_cast<const float4*>(p_); \
        float4 f1_ = *reinterpret_cast<const float4*>(p_ + 4); \
        xv[0]=f0_.x; xv[1]=f0_.y; xv[2]=f0_.z; xv[3]=f0_.w; \
        xv[4]=f1_.x; xv[5]=f1_.y; xv[6]=f1_.z; xv[7]=f1_.w; \
    } else { \
        _Pragma("unroll") for (int j_ = 0; j_ < 8; j_++) xv[j_] = 0.f; \
    } \
} while (0)

#define STORE_A(BUF) do { \
    if (tid < 256) { \
        uint32_t hq_[4], lq_[4]; \
        _Pragma("unroll") \
        for (int j_ = 0; j_ < 4; j_++) { \
            __nv_bfloat16 h0_ = __float2bfloat16(xv[2*j_]); \
            __nv_bfloat16 h1_ = __float2bfloat16(xv[2*j_+1]); \
            __nv_bfloat16 l0_ = __float2bfloat16(xv[2*j_]   - __bfloat162float(h0_)); \
            __nv_bfloat16 l1_ = __float2bfloat16(xv[2*j_+1] - __bfloat162float(h1_)); \
            hq_[j_] = pk2(h0_, h1_); \
            lq_[j_] = pk2(l0_, l1_); \
        } \
        char* aH = smem + SMM_A + (BUF) * 10240 + xrow * 80 + xkc * 16; \
        *reinterpret_cast<uint4*>(aH)        = make_uint4(hq_[0], hq_[1], hq_[2], hq_[3]); \
        *reinterpret_cast<uint4*>(aH + 5120) = make_uint4(lq_[0], lq_[1], lq_[2], lq_[3]); \
    } \
} while (0)

    ISSUE_W(0, 0); CP_COMMIT();
    LOAD_X(0);
    ISSUE_W(1, 1); CP_COMMIT();
    STORE_A(0);
    LOAD_X(1);

    for (int ch = 0; ch < NCH; ch++) {
        int buf = ch & 1;
        if (ch > 0) {
            STORE_A(buf);
            if (ch + 1 < NCH) LOAD_X(ch + 1);
        }
        CP_WAIT1();
        __syncthreads();

        const uint32_t* AH  = reinterpret_cast<const uint32_t*>(smem + SMM_A + buf * 10240);
        const uint32_t* AL  = AH + 1280;
        const uint32_t* WHs = reinterpret_cast<const uint32_t*>(smem + SMM_W + buf * 81920);
        const uint32_t* WLs = WHs + 10240;

        #pragma unroll
        for (int h = 0; h < 2; h++) {
            uint32_t ah[2][4], al[2][4];
            #pragma unroll
            for (int mt = 0; mt < 2; mt++) {
                int base = (wm * 32 + mt * 16 + g) * 20 + h * 8 + tig;
                ah[mt][0] = AH[base];     ah[mt][1] = AH[base + 160];
                ah[mt][2] = AH[base + 4]; ah[mt][3] = AH[base + 164];
                al[mt][0] = AL[base];     al[mt][1] = AL[base + 160];
                al[mt][2] = AL[base + 4]; al[mt][3] = AL[base + 164];
            }
            #pragma unroll
            for (int nt = 0; nt < 8; nt++) {
                int wb = (wn * 64 + nt * 8 + g) * 20 + h * 8 + tig;
                uint32_t b0h = WHs[wb], b1h = WHs[wb + 4];
                uint32_t b0l = WLs[wb], b1l = WLs[wb + 4];
                // product-pass outer, mt inner: same-acc MMAs separated
                mma16816(acc[0][nt], ah[0], b0h, b1h);
                mma16816(acc[1][nt], ah[1], b0h, b1h);
                mma16816(acc[0][nt], ah[0], b0l, b1l);
                mma16816(acc[1][nt], ah[1], b0l, b1l);
                mma16816(acc[0][nt], al[0], b0h, b1h);
                mma16816(acc[1][nt], al[1], b0h, b1h);
            }
        }
        __syncthreads();
        if (ch + 2 < NCH) ISSUE_W(ch + 2, buf);
        CP_COMMIT();
    }

    // epilogue: bias + L2 norm + 9 prompt dots (two N-halves staged in ysm)
    for (int half = 0; half < 2; half++) {
        if ((wn >> 2) == half) {
            #pragma unroll
            for (int mt = 0; mt < 2; mt++) {
                int row = wm * 32 + mt * 16 + g;
                #pragma unroll
                for (int nt = 0; nt < 8; nt++) {
                    int col = wn * 64 + nt * 8 + tig * 2;
                    int colrel = col - half * 256;
                    float b0 = Sbi[col], b1 = Sbi[col + 1];
                    *reinterpret_cast<float2*>(&ysm[row * Y_STR + colrel]) =
                        make_float2(acc[mt][nt][0] + b0, acc[mt][nt][1] + b1);
                    *reinterpret_cast<float2*>(&ysm[(row + 8) * Y_STR + colrel]) =
                        make_float2(acc[mt][nt][2] + b0, acc[mt][nt][3] + b1);
                }
            }
        }
        __syncthreads();
        for (int r4 = 0; r4 < 4; r4++) {
            int row = wid * 4 + r4;
            float v[10];
            #pragma unroll
            for (int j = 0; j < 10; j++) v[j] = 0.f;
            for (int cc = lane; cc < 256; cc += 32) {
                float y = ysm[row * Y_STR + cc];
                int col = half * 256 + cc;
                v[0] += y * y;
                #pragma unroll
                for (int n = 0; n < NE; n++) v[1 + n] += y * Psm[n * 512 + col];
            }
            #pragma unroll
            for (int j = 0; j < 10; j++)
                #pragma unroll
                for (int off = 16; off; off >>= 1) v[j] += __shfl_xor_sync(0xffffffffu, v[j], off);
            if (lane == 0) {
                #pragma unroll
                for (int j = 0; j < 10; j++) red[row * 10 + j] += v[j];
            }
        }
        __syncthreads();
    }

    if (tid < 64) {
        int s = s0 + tid;
        if (s < S_SP) {
            float inv = rsqrtf(red[tid * 10]);
            size_t base = ((size_t)(i * T_TOK + t) * NE) * S_SP + s;
            #pragma unroll
            for (int n = 0; n < NE; n++)
                g_scores[base + (size_t)n * S_SP] = 100.f * red[tid * 10 + 1 + n] * inv;
        }
    }
#undef ISSUE_W
#undef LOAD_X
#undef STORE_A
}

__global__ void k_softmax_mean() {
    int tn = blockIdx.x;
    int t = tn / NE, n = tn % NE;
    int tid = threadIdx.x;
    float accm[3] = {0.f, 0.f, 0.f};
    for (int i = 0; i < NL; i++) {
        size_t base = ((size_t)(i * T_TOK + t) * NE + n) * S_SP;
        float x[3];
        float mx = -INFINITY;
        #pragma unroll
        for (int j = 0; j < 3; j++) {
            int s = tid + j * 256;
            x[j] = (s < S_SP) ? g_scores[base + s] : -INFINITY;
            mx = fmaxf(mx, x[j]);
        }
        mx = blockMax256(mx);
        float lsum = 0.f;
        float e[3];
        #pragma unroll
        for (int j = 0; j < 3; j++) {
            int s = tid + j * 256;
            e[j] = (s < S_SP) ? expf(x[j] - mx) : 0.f;
            lsum += e[j];
        }
        float tot = blockSum256(lsum);
        float inv = 0.25f / tot;
        #pragma unroll
        for (int j = 0; j < 3; j++) accm[j] += e[j] * inv;
    }
    float psum = 0.f;
    size_t obase = ((size_t)t * NE + n) * S_SP;
    #pragma unroll
    for (int j = 0; j < 3; j++) {
        int s = tid + j * 256;
        if (s < S_SP) {
            g_meanatt[obase + s] = accm[j];
            psum += accm[j];
        }
    }
    float tot = blockSum256(psum);
    if (tid == 0) g_pes[t * NE + n] = tot / (float)S_SP;
}

__global__ void k_tail(const float* __restrict__ ov,
                       const float* __restrict__ qw, const float* __restrict__ qb,
                       const float* __restrict__ kw, const float* __restrict__ kb,
                       float* __restrict__ out) {
    extern __shared__ float S[];
    float* matt = S;
    float* sp   = S + 736;
    float* qkb  = S + 740;
    float* pmx  = S + 744;
    float* toks = S + 752;
    float* Qs   = toks + 4608;
    float* KQs  = Qs + 2048;
    float* law  = KQs + 4608;

    int t = blockIdx.x, tid = threadIdx.x;
    int wid = tid >> 5, lane = tid & 31;

    float bsum[4] = {0.f, 0.f, 0.f, 0.f};
    for (int s = tid; s < S_SP; s += 256) {
        float m = -INFINITY;
        #pragma unroll
        for (int n = 0; n < NE; n++)
            m = fmaxf(m, g_meanatt[((size_t)t * NE + n) * S_SP + s]);
        matt[s] = m;
        int r = s / 27, c = s - r * 27;
        bool r0 = r < 14, r1 = r >= 13, c0 = c < 14, c1 = c >= 13;
        if (r0 && c0) bsum[0] += m;
        if (r0 && c1) bsum[1] += m;
        if (r1 && c0) bsum[2] += m;
        if (r1 && c1) bsum[3] += m;
    }
    #pragma unroll
    for (int q = 0; q < 4; q++) {
        float tot = blockSum256(bsum[q]);
        if (tid == 0) sp[q] = tot / 196.f;
    }
    if (tid == 0) {
        float pm = -INFINITY;
        for (int n = 0; n < NE; n++) pm = fmaxf(pm, g_pes[t * NE + n]);
        pmx[0] = pm;
    }
    __syncthreads();
    if (tid < 4) g_gsig[t * 4 + tid] = sp[tid] * pmx[0];

    {
        int nh = (tid < 128) ? 5 : 4;
        float accT[5][4];
        #pragma unroll
        for (int j = 0; j < 5; j++)
            #pragma unroll
            for (int q = 0; q < 4; q++) accT[j][q] = 0.f;
        const float* obase = ov + ((size_t)t * S_SP) * H_DIM + tid;
        for (int s = 0; s < S_SP; s++) {
            float a = matt[s];
            int r = s / 27, c = s - r * 27;
            float w0 = (r < 14 && c < 14) ? a : 0.f;
            float w1 = (r < 14 && c >= 13) ? a : 0.f;
            float w2 = (r >= 13 && c < 14) ? a : 0.f;
            float w3 = (r >= 13 && c >= 13) ? a : 0.f;
            const float* p = obase + (size_t)s * H_DIM;
            #pragma unroll
            for (int j = 0; j < 5; j++) {
                if (j < nh) {
                    float v = p[j * 256];
                    accT[j][0] += v * w0;
                    accT[j][1] += v * w1;
                    accT[j][2] += v * w2;
                    accT[j][3] += v * w3;
                }
            }
        }
        for (int j = 0; j < nh; j++) {
            int h = tid + j * 256;
            #pragma unroll
            for (int q = 0; q < 4; q++)
                toks[q * H_DIM + h] = (accT[j][q] * (1.f / 196.f)) / (sp[q] + 1e-8f);
        }
    }
    __syncthreads();

    for (int o = wid; o < E_DIM; o += 8) {
        float acc[4] = {0.f, 0.f, 0.f, 0.f};
        const float* wr = qw + (size_t)o * H_DIM;
        for (int k = lane; k < H_DIM; k += 32) {
            float w = wr[k];
            #pragma unroll
            for (int q = 0; q < 4; q++) acc[q] += w * toks[q * H_DIM + k];
        }
        #pragma unroll
        for (int off = 16; off; off >>= 1)
            #pragma unroll
            for (int q = 0; q < 4; q++) acc[q] += __shfl_xor_sync(0xffffffffu, acc[q], off);
        if (lane == 0) {
            float bv = qb[o];
            #pragma unroll
            for (int q = 0; q < 4; q++) Qs[q * E_DIM + o] = acc[q] + bv;
        }
    }
    __syncthreads();
    if (wid < 4) {
        float acc = 0.f;
        for (int e = lane; e < E_DIM; e += 32) acc += Qs[wid * E_DIM + e] * kb[e];
        #pragma unroll
        for (int off = 16; off; off >>= 1) acc += __shfl_xor_sync(0xffffffffu, acc, off);
        if (lane == 0) qkb[wid] = acc;
    }
    __syncthreads();

    {
        float a[5][4];
        #pragma unroll
        for (int j = 0; j < 5; j++)
            #pragma unroll
            for (int q = 0; q < 4; q++) a[j][q] = 0.f;
        for (int e = 0; e < E_DIM; e++) {
            float q0 = Qs[e], q1 = Qs[512 + e], q2 = Qs[1024 + e], q3 = Qs[1536 + e];
            const float* kr = kw + (size_t)e * H_DIM;
            #pragma unroll
            for (int j = 0; j < 5; j++) {
                int h = j * 256 + tid;
                if (h < H_DIM) {
                    float kv = kr[h];
                    a[j][0] += kv * q0; a[j][1] += kv * q1;
                    a[j][2] += kv * q2; a[j][3] += kv * q3;
                }
            }
        }
        #pragma unroll
        for (int j = 0; j < 5; j++) {
            int h = j * 256 + tid;
            if (h < H_DIM) {
                #pragma unroll
                for (int q = 0; q < 4; q++) KQs[q * H_DIM + h] = a[j][q];
            }
        }
    }
    __syncthreads();

    const float RS = 0.04419417382415922f;
    for (int s = wid; s < S_SP; s += 8) {
        float acc[4] = {0.f, 0.f, 0.f, 0.f};
        const float* orow = ov + ((size_t)t * S_SP + s) * H_DIM;
        for (int h = lane; h < H_DIM; h += 32) {
            float vv = orow[h];
            #pragma unroll
            for (int q = 0; q < 4; q++) acc[q] += vv * KQs[q * H_DIM + h];
        }
        #pragma unroll
        for (int off = 16; off; off >>= 1)
            #pragma unroll
            for (int q = 0; q < 4; q++) acc[q] += __shfl_xor_sync(0xffffffffu, acc[q], off);
        if (lane == 0) {
            #pragma unroll
            for (int q = 0; q < 4; q++) law[q * S_SP + s] = (acc[q] + qkb[q]) * RS;
        }
    }
    __syncthreads();
    for (int q = 0; q < 4; q++) {
        float mx = -INFINITY;
        for (int s = tid; s < S_SP; s += 256) mx = fmaxf(mx, law[q * S_SP + s]);
        mx = blockMax256(mx);
        float lsum = 0.f;
        for (int s = tid; s < S_SP; s += 256) {
            float e = expf(law[q * S_SP + s] - mx);
            law[q * S_SP + s] = e;
            lsum += e;
        }
        float tot = blockSum256(lsum);
        float inv = 1.f / tot;
        for (int s = tid; s < S_SP; s += 256) law[q * S_SP + s] *= inv;
        __syncthreads();
    }

    {
        int nh = (tid < 128) ? 5 : 4;
        float macc[5][4];
        #pragma unroll
        for (int j = 0; j < 5; j++)
            #pragma unroll
            for (int q = 0; q < 4; q++) macc[j][q] = 0.f;
        const float* obase = ov + ((size_t)t * S_SP) * H_DIM + tid;
        for (int s = 0; s < S_SP; s++) {
            float a0 = law[0 * S_SP + s], a1 = law[1 * S_SP + s];
            float a2 = law[2 * S_SP + s], a3 = law[3 * S_SP + s];
            const float* p = obase + (size_t)s * H_DIM;
            #pragma unroll
            for (int j = 0; j < 5; j++) {
                if (j < nh) {
                    float v = p[j * 256];
                    macc[j][0] += a0 * v;
                    macc[j][1] += a1 * v;
                    macc[j][2] += a2 * v;
                    macc[j][3] += a3 * v;
                }
            }
        }
        for (int j = 0; j < nh; j++) {
            int h = tid + j * 256;
            #pragma unroll
            for (int q = 0; q < 4; q++)
                out[OUT_MAJOR + ((size_t)t * 4 + q) * H_DIM + h] = macc[j][q];
        }
    }
}

__global__ void k_finpred(const float* __restrict__ w1, const float* __restrict__ b1,
                          const float* __restrict__ w2, const float* __restrict__ b2,
                          float* __restrict__ out) {
    int b = blockIdx.x, tid = threadIdx.x;
    __shared__ float gsh[32];
    __shared__ float gsum_sh;
    __shared__ float fr[H_DIM];
    __shared__ float hid[E_DIM];
    __shared__ float lg[NE];
    if (tid < 32) {
        int p = tid >> 2, q = tid & 3;
        gsh[tid] = g_gsig[(b * P_PAT + p) * 4 + q];
    }
    __syncthreads();
    if (tid == 0) {
        float s = 0.f;
        for (int i = 0; i < 32; i++) s += gsh[i];
        gsum_sh = s;
    }
    __syncthreads();
    float denom = gsum_sh / 32.f + 1e-8f;
    int nh = (tid < 128) ? 5 : 4;
    for (int j = 0; j < nh; j++) {
        int h = tid + j * 256;
        float acc = 0.f;
        for (int idx = 0; idx < 32; idx++) {
            int p = idx >> 2, q = idx & 3;
            acc += out[OUT_MAJOR + ((size_t)(b * P_PAT + p) * 4 + q) * H_DIM + h] * gsh[idx];
        }
        float fin = (acc / 32.f) / denom;
        fr[h] = fin;
        out[OUT_FINAL + (size_t)b * H_DIM + h] = fin;
    }
    __syncthreads();
    int wid = tid >> 5, lane = tid & 31;
    for (int o = wid; o < E_DIM; o += 8) {
        float acc = 0.f;
        const float* wr = w1 + (size_t)o * H_DIM;
        for (int k = lane; k < H_DIM; k += 32) acc += wr[k] * fr[k];
        #pragma unroll
        for (int off = 16; off; off >>= 1) acc += __shfl_xor_sync(0xffffffffu, acc, off);
        if (lane == 0) hid[o] = gelu_exact(acc + b1[o]);
    }
    __syncthreads();
    for (int n = 0; n < NE; n++) {
        float v = hid[tid] * w2[n * E_DIM + tid] + hid[tid + 256] * w2[n * E_DIM + tid + 256];
        float tot = blockSum256(v);
        if (tid == 0) lg[n] = tot + b2[n];
    }
    __syncthreads();
    if (tid == 0) {
        float mx = -INFINITY;
        for (int n = 0; n < NE; n++) mx = fmaxf(mx, lg[n]);
        float sum = 0.f;
        float e[NE];
        for (int n = 0; n < NE; n++) { e[n] = expf(lg[n] - mx); sum += e[n]; }
        for (int n = 0; n < NE; n++) out[OUT_PREDS + b * NE + n] = e[n] / sum;
    }
}

extern "C" void kernel_launch(void* const* d_in, const int* in_sizes, int n_in,
                              void* d_out, int out_size) {
    const float* ov      = (const float*)d_in[0];
    const float* sig     = (const float*)d_in[1];
    const float* emo     = (const float*)d_in[2];
    const float* pool_w  = (const float*)d_in[3];
    const float* pool_b  = (const float*)d_in[4];
    const float* cls_w1  = (const float*)d_in[5];
    const float* cls_b1  = (const float*)d_in[6];
    const float* cls_w2  = (const float*)d_in[7];
    const float* cls_b2  = (const float*)d_in[8];
    const float* sig_w   = (const float*)d_in[9];
    const float* sig_b   = (const float*)d_in[10];
    const float* prm_w   = (const float*)d_in[11];
    const float* prm_b   = (const float*)d_in[12];
    const float* pred_w1 = (const float*)d_in[13];
    const float* pred_b1 = (const float*)d_in[14];
    const float* pred_w2 = (const float*)d_in[15];
    const float* pred_b2 = (const float*)d_in[16];
    const float* q_w     = (const float*)d_in[17];
    const float* q_b     = (const float*)d_in[18];
    const float* k_w     = (const float*)d_in[19];
    const float* k_b     = (const float*)d_in[20];
    float* out = (float*)d_out;

    cudaFuncSetAttribute(k_sig_mma, cudaFuncAttributeMaxDynamicSharedMemorySize, SMM_TOTAL);
    cudaFuncSetAttribute(k_tail, cudaFuncAttributeMaxDynamicSharedMemorySize, 61440);
    cudaFuncSetAttribute(k_pre2, cudaFuncAttributeMaxDynamicSharedMemorySize, 90112);

    k_wsplit<<<1024, 256>>>(sig_w);                                   // 0
    k_pre1<<<dim3(B_IMG, 9), 128>>>(ov, pool_w);                      // 1
    k_pre2<<<1, 512, 90112>>>(cls_w1, cls_b1, pool_b, cls_w2, cls_b2,
                              emo, prm_w, prm_b);                      // 2
    k_sig_mma<<<dim3(12, T_TOK, NL), 512, SMM_TOTAL>>>(sig, sig_b);   // 3  <- ncu slot
    k_softmax_mean<<<T_TOK * NE, 256>>>();                             // 4
    k_tail<<<T_TOK, 256, 61440>>>(ov, q_w, q_b, k_w, k_b, out);        // 5
    k_finpred<<<B_IMG, 256>>>(pred_w1, pred_b1, pred_w2, pred_b2, out);// 6
}

// round 10
// speedup vs baseline: 1.2316x; 1.2316x over previous
#include <cuda_runtime.h>
#include <cuda_bf16.h>
#include <math.h>
#include <stdint.h>

#define T_TOK 64
#define S_SP  729
#define H_DIM 1152
#define E_DIM 512
#define NE    9
#define NL    4
#define B_IMG 8
#define P_PAT 8

#define OUT_MAJOR 0
#define OUT_FINAL (T_TOK * 4 * H_DIM)
#define OUT_PREDS (OUT_FINAL + B_IMG * H_DIM)

__device__ float g_poolpart[B_IMG * 9 * H_DIM];
__device__ float g_hidden [B_IMG * E_DIM];
__device__ float g_cls    [B_IMG * E_DIM];
__device__ float g_puv    [NL * 17 * E_DIM];
__device__ float g_prompts[NL * B_IMG * NE * E_DIM];
__device__ float g_part   [(size_t)NL * T_TOK * 2 * 10 * S_SP];   // 14.9 MB
__device__ float g_meanatt[T_TOK * NE * S_SP];
__device__ float g_pes    [T_TOK * NE];
__device__ float g_gsig   [T_TOK * 4];
__device__ __align__(16) __nv_bfloat16 g_Whi[(size_t)NL * E_DIM * H_DIM];
__device__ __align__(16) __nv_bfloat16 g_Wlo[(size_t)NL * E_DIM * H_DIM];

__device__ __forceinline__ uint32_t smem_u32(const void* p) {
    uint32_t a;
    asm("{ .reg .u64 t; cvta.to.shared.u64 t, %1; cvt.u32.u64 %0, t; }" : "=r"(a) : "l"(p));
    return a;
}
__device__ __forceinline__ void cpasync16(uint32_t dst, const void* src) {
    asm volatile("cp.async.cg.shared.global [%0], [%1], 16;" :: "r"(dst), "l"(src));
}
#define CP_COMMIT() asm volatile("cp.async.commit_group;" ::: "memory")
#define CP_WAIT1()  asm volatile("cp.async.wait_group 1;" ::: "memory")

__device__ __forceinline__ float blockSum256(float v) {
    __shared__ float red[8];
    int lane = threadIdx.x & 31, wid = threadIdx.x >> 5;
    #pragma unroll
    for (int o = 16; o; o >>= 1) v += __shfl_xor_sync(0xffffffffu, v, o);
    if (lane == 0) red[wid] = v;
    __syncthreads();
    if (wid == 0) {
        float r = (lane < 8) ? red[lane] : 0.f;
        #pragma unroll
        for (int o = 4; o; o >>= 1) r += __shfl_xor_sync(0xffffffffu, r, o);
        if (lane == 0) red[0] = r;
    }
    __syncthreads();
    float r = red[0];
    __syncthreads();
    return r;
}
__device__ __forceinline__ float blockMax256(float v) {
    __shared__ float red[8];
    int lane = threadIdx.x & 31, wid = threadIdx.x >> 5;
    #pragma unroll
    for (int o = 16; o; o >>= 1) v = fmaxf(v, __shfl_xor_sync(0xffffffffu, v, o));
    if (lane == 0) red[wid] = v;
    __syncthreads();
    if (wid == 0) {
        float r = (lane < 8) ? red[lane] : -INFINITY;
        #pragma unroll
        for (int o = 4; o; o >>= 1) r = fmaxf(r, __shfl_xor_sync(0xffffffffu, r, o));
        if (lane == 0) red[0] = r;
    }
    __syncthreads();
    float r = red[0];
    __syncthreads();
    return r;
}
__device__ __forceinline__ float gelu_exact(float x) {
    return 0.5f * x * (1.0f + erff(x * 0.7071067811865475f));
}
__device__ __forceinline__ uint32_t pk2(__nv_bfloat16 a, __nv_bfloat16 b) {
    return ((uint32_t)__bfloat16_as_ushort(b) << 16) | (uint32_t)__bfloat16_as_ushort(a);
}
__device__ __forceinline__ void mma16816(float* d, const uint32_t* a, uint32_t b0, uint32_t b1) {
    asm volatile(
        "mma.sync.aligned.m16n8k16.row.col.f32.bf16.bf16.f32 "
        "{%0,%1,%2,%3}, {%4,%5,%6,%7}, {%8,%9}, {%0,%1,%2,%3};"
        : "+f"(d[0]), "+f"(d[1]), "+f"(d[2]), "+f"(d[3])
        : "r"(a[0]), "r"(a[1]), "r"(a[2]), "r"(a[3]), "r"(b0), "r"(b1));
}

__global__ void k_wsplit(const float* __restrict__ sw) {
    const size_t N = (size_t)NL * E_DIM * H_DIM;
    for (size_t i = (size_t)blockIdx.x * 256 + threadIdx.x; i < N; i += (size_t)gridDim.x * 256) {
        float w = sw[i];
        __nv_bfloat16 h = __float2bfloat16(w);
        g_Whi[i] = h;
        g_Wlo[i] = __float2bfloat16(w - __bfloat162float(h));
    }
}

__global__ void k_pool(const float* __restrict__ ov, const float* __restrict__ pw) {
    int b = blockIdx.x, sc = blockIdx.y, tid = threadIdx.x;
    float acc[9];
    #pragma unroll
    for (int j = 0; j < 9; j++) acc[j] = 0.f;
    const float* base = ov + (size_t)(b * P_PAT) * S_SP * H_DIM + (size_t)sc * 81 * H_DIM + tid;
    for (int s = 0; s < 81; s++) {
        float w = pw[sc * 81 + s];
        const float* p = base + (size_t)s * H_DIM;
        #pragma unroll
        for (int j = 0; j < 9; j++) acc[j] += w * p[j * 128];
    }
    #pragma unroll
    for (int j = 0; j < 9; j++)
        g_poolpart[((size_t)b * 9 + sc) * H_DIM + tid + j * 128] = acc[j];
}

__global__ void k_cls1(const float* __restrict__ w1, const float* __restrict__ b1,
                       const float* __restrict__ pb) {
    __shared__ float pr[B_IMG * H_DIM];
    int tid = threadIdx.x, wid = tid >> 5, lane = tid & 31;
    float pbias = pb[0];
    for (int idx = tid; idx < B_IMG * H_DIM; idx += 256) {
        int b = idx / H_DIM, h = idx - b * H_DIM;
        float s = pbias;
        #pragma unroll
        for (int sc = 0; sc < 9; sc++) s += g_poolpart[((size_t)b * 9 + sc) * H_DIM + h];
        pr[idx] = s;
    }
    __syncthreads();
    int o = blockIdx.x * 8 + wid;
    float acc[8];
    #pragma unroll
    for (int b = 0; b < 8; b++) acc[b] = 0.f;
    const float* wr = w1 + (size_t)o * H_DIM;
    for (int k = lane; k < H_DIM; k += 32) {
        float w = wr[k];
        #pragma unroll
        for (int b = 0; b < 8; b++) acc[b] += w * pr[b * H_DIM + k];
    }
    #pragma unroll
    for (int b = 0; b < 8; b++)
        #pragma unroll
        for (int off = 16; off; off >>= 1) acc[b] += __shfl_xor_sync(0xffffffffu, acc[b], off);
    if (lane == 0) {
        float bv = b1[o];
        #pragma unroll
        for (int b = 0; b < 8; b++) g_hidden[b * E_DIM + o] = gelu_exact(acc[b] + bv);
    }
}

__global__ void k_cls2(const float* __restrict__ w2, const float* __restrict__ b2) {
    __shared__ float hr[B_IMG * E_DIM];
    int tid = threadIdx.x, wid = tid >> 5, lane = tid & 31;
    for (int idx = tid; idx < B_IMG * E_DIM; idx += 256) hr[idx] = g_hidden[idx];
    __syncthreads();
    int o = blockIdx.x * 8 + wid;
    float acc[8];
    #pragma unroll
    for (int b = 0; b < 8; b++) acc[b] = 0.f;
    const float* wr = w2 + (size_t)o * E_DIM;
    for (int k = lane; k < E_DIM; k += 32) {
        float w = wr[k];
        #pragma unroll
        for (int b = 0; b < 8; b++) acc[b] += w * hr[b * E_DIM + k];
    }
    #pragma unroll
    for (int b = 0; b < 8; b++)
        #pragma unroll
        for (int off = 16; off; off >>= 1) acc[b] += __shfl_xor_sync(0xffffffffu, acc[b], off);
    if (lane == 0) {
        float bv = b2[o];
        #pragma unroll
        for (int b = 0; b < 8; b++) g_cls[b * E_DIM + o] = acc[b] + bv;
    }
}

__global__ void k_puv(const float* __restrict__ emo, const float* __restrict__ pw) {
    int oc = blockIdx.x, i = blockIdx.y;
    int tid = threadIdx.x, wid = tid >> 5, lane = tid & 31;
    __shared__ float es[NE * E_DIM];
    __shared__ float cs[B_IMG * E_DIM];
    for (int idx = tid; idx < NE * E_DIM; idx += 256) es[idx] = emo[idx];
    for (int idx = tid; idx < B_IMG * E_DIM; idx += 256) cs[idx] = g_cls[idx];
    __syncthreads();
    for (int oi = wid; oi < 32; oi += 8) {
        int o = oc * 32 + oi;
        const float* wr = pw + ((size_t)i * E_DIM + o) * 1024;
        float acc[17];
        #pragma unroll
        for (int j = 0; j < 17; j++) acc[j] = 0.f;
        for (int c = lane; c < 512; c += 32) {
            float w1 = wr[c];
            #pragma unroll
            for (int n = 0; n < NE; n++) acc[n] += w1 * es[n * 512 + c];
            float w2 = wr[512 + c];
            #pragma unroll
            for (int b = 0; b < B_IMG; b++) acc[9 + b] += w2 * cs[b * 512 + c];
        }
        #pragma unroll
        for (int j = 0; j < 17; j++)
            #pragma unroll
            for (int off = 16; off; off >>= 1) acc[j] += __shfl_xor_sync(0xffffffffu, acc[j], off);
        if (lane == 0) {
            #pragma unroll
            for (int j = 0; j < 17; j++) g_puv[((size_t)i * 17 + j) * 512 + o] = acc[j];
        }
    }
}

__global__ void k_prompts2(const float* __restrict__ pb) {
    int n = blockIdx.x, b = blockIdx.y, i = blockIdx.z;
    int tid = threadIdx.x;
    int o1 = tid, o2 = tid + 256;
    float r1 = g_puv[((size_t)i * 17 + n) * 512 + o1] + g_puv[((size_t)i * 17 + 9 + b) * 512 + o1]
             + pb[i * 512 + o1];
    float r2 = g_puv[((size_t)i * 17 + n) * 512 + o2] + g_puv[((size_t)i * 17 + 9 + b) * 512 + o2]
             + pb[i * 512 + o2];
    float nrm = blockSum256(r1 * r1 + r2 * r2);
    float inv = rsqrtf(nrm);
    size_t base = ((size_t)(i * B_IMG + b) * NE + n) * E_DIM;
    g_prompts[base + o1] = r1 * inv;
    g_prompts[base + o2] = r2 * inv;
}

// ======= sig GEMM, N split in half for 2 CTAs/SM: grid (12, 64, 8), block 256 =======
// blockIdx.z = i*2 + half. Tile: M=64, N=256(half), kstep=32. Partials -> g_part.
#define NCH 36
#define SM2_PSM   0          // 9*256*4    = 9216
#define SM2_SBI   9216       // 256*4      = 1024
#define SM2_RED   10240      // 64*10*4    = 2560
#define SM2_A     12800      // 2 x (hi 5120 + lo 5120) = 20480
#define SM2_W     33280      // 2 x (hi 20480 + lo 20480) = 81920
#define SM2_YSM   12800      // union over A+W (epilogue): 64*260*4 = 66560
#define SM2_TOTAL 115200
#define Y_STR 260

__global__ void __launch_bounds__(256, 2)
k_sig_mma(const float* __restrict__ sig, const float* __restrict__ sb) {
    extern __shared__ char smem[];
    uint32_t sbase = smem_u32(smem);
    float* Psm = reinterpret_cast<float*>(smem + SM2_PSM);
    float* Sbi = reinterpret_cast<float*>(smem + SM2_SBI);
    float* red = reinterpret_cast<float*>(smem + SM2_RED);
    float* ysm = reinterpret_cast<float*>(smem + SM2_YSM);

    int tid = threadIdx.x, wid = tid >> 5, lane = tid & 31;
    int wm = wid >> 2, wn = wid & 3;       // 2m x 4n; warp tile 32 rows x 64 cols
    int g = lane >> 2, tig = lane & 3;
    int s0 = blockIdx.x * 64;
    int t = blockIdx.y;
    int i = blockIdx.z >> 1, half = blockIdx.z & 1;
    int b = t >> 3;

    {
        size_t pbase = ((size_t)(i * B_IMG + b) * NE) * E_DIM + half * 256;
        for (int idx = tid; idx < NE * 256; idx += 256) {
            int n = idx >> 8, cc = idx & 255;
            Psm[idx] = g_prompts[pbase + (size_t)n * E_DIM + cc];
        }
        for (int idx = tid; idx < 256; idx += 256) Sbi[idx] = sb[i * E_DIM + half * 256 + idx];
        for (int idx = tid; idx < 640; idx += 256) red[idx] = 0.f;
    }

    const float* Xbase = sig + ((size_t)(i * T_TOK + t) * S_SP) * H_DIM;
    const char* WH = reinterpret_cast<const char*>(g_Whi)
                   + ((size_t)i * E_DIM + half * 256) * H_DIM * 2;
    const char* WL = reinterpret_cast<const char*>(g_Wlo)
                   + ((size_t)i * E_DIM + half * 256) * H_DIM * 2;

    float acc[2][8][4];
    #pragma unroll
    for (int mt = 0; mt < 2; mt++)
        #pragma unroll
        for (int nt = 0; nt < 8; nt++)
            #pragma unroll
            for (int c = 0; c < 4; c++) acc[mt][nt][c] = 0.f;

    int xrow = tid >> 2, xkc = tid & 3;
    int xs = s0 + xrow;
    const float* xptr = (xs < S_SP) ? (Xbase + (size_t)xs * H_DIM + xkc * 8) : nullptr;
    float xv[8];

#define ISSUE_W(CH, BUF) do { \
    uint32_t wHi = sbase + SM2_W + (BUF) * 40960; \
    int n_ = tid; \
    const char* sH = WH + ((size_t)n_ * H_DIM + (CH) * 32) * 2; \
    const char* sL = WL + ((size_t)n_ * H_DIM + (CH) * 32) * 2; \
    uint32_t dH = wHi + n_ * 80; \
    uint32_t dL = dH + 20480; \
    cpasync16(dH, sH); cpasync16(dH + 16, sH + 16); \
    cpasync16(dH + 32, sH + 32); cpasync16(dH + 48, sH + 48); \
    cpasync16(dL, sL); cpasync16(dL + 16, sL + 16); \
    cpasync16(dL + 32, sL + 32); cpasync16(dL + 48, sL + 48); \
} while (0)

#define LOAD_X(CH) do { \
    if (xptr) { \
        const float* p_ = xptr + (CH) * 32; \
        float4 f0_ = *reinterpret_cast<const float4*>(p_); \
        float4 f1_ = *reinterpret_cast<const float4*>(p_ + 4); \
        xv[0]=f0_.x; xv[1]=f0_.y; xv[2]=f0_.z; xv[3]=f0_.w; \
        xv[4]=f1_.x; xv[5]=f1_.y; xv[6]=f1_.z; xv[7]=f1_.w; \
    } else { \
        _Pragma("unroll") for (int j_ = 0; j_ < 8; j_++) xv[j_] = 0.f; \
    } \
} while (0)

#define STORE_A(BUF) do { \
    uint32_t hq_[4], lq_[4]; \
    _Pragma("unroll") \
    for (int j_ = 0; j_ < 4; j_++) { \
        __nv_bfloat16 h0_ = __float2bfloat16(xv[2*j_]); \
        __nv_bfloat16 h1_ = __float2bfloat16(xv[2*j_+1]); \
        __nv_bfloat16 l0_ = __float2bfloat16(xv[2*j_]   - __bfloat162float(h0_)); \
        __nv_bfloat16 l1_ = __float2bfloat16(xv[2*j_+1] - __bfloat162float(h1_)); \
        hq_[j_] = pk2(h0_, h1_); \
        lq_[j_] = pk2(l0_, l1_); \
    } \
    char* aH = smem + SM2_A + (BUF) * 10240 + xrow * 80 + xkc * 16; \
    *reinterpret_cast<uint4*>(aH)        = make_uint4(hq_[0], hq_[1], hq_[2], hq_[3]); \
    *reinterpret_cast<uint4*>(aH + 5120) = make_uint4(lq_[0], lq_[1], lq_[2], lq_[3]); \
} while (0)

    ISSUE_W(0, 0); CP_COMMIT();
    LOAD_X(0);
    ISSUE_W(1, 1); CP_COMMIT();
    STORE_A(0);
    LOAD_X(1);

    for (int ch = 0; ch < NCH; ch++) {
        int buf = ch & 1;
        if (ch > 0) {
            STORE_A(buf);
            if (ch + 1 < NCH) LOAD_X(ch + 1);
        }
        CP_WAIT1();
        __syncthreads();

        const uint32_t* AH  = reinterpret_cast<const uint32_t*>(smem + SM2_A + buf * 10240);
        const uint32_t* AL  = AH + 1280;
        const uint32_t* WHs = reinterpret_cast<const uint32_t*>(smem + SM2_W + buf * 40960);
        const uint32_t* WLs = WHs + 5120;

        #pragma unroll
        for (int h = 0; h < 2; h++) {
            uint32_t ah[2][4], al[2][4];
            #pragma unroll
            for (int mt = 0; mt < 2; mt++) {
                int base = (wm * 32 + mt * 16 + g) * 20 + h * 8 + tig;
                ah[mt][0] = AH[base];     ah[mt][1] = AH[base + 160];
                ah[mt][2] = AH[base + 4]; ah[mt][3] = AH[base + 164];
                al[mt][0] = AL[base];     al[mt][1] = AL[base + 160];
                al[mt][2] = AL[base + 4]; al[mt][3] = AL[base + 164];
            }
            #pragma unroll
            for (int nt = 0; nt < 8; nt++) {
                int wb = (wn * 64 + nt * 8 + g) * 20 + h * 8 + tig;
                uint32_t b0h = WHs[wb], b1h = WHs[wb + 4];
                uint32_t b0l = WLs[wb], b1l = WLs[wb + 4];
                #pragma unroll
                for (int mt = 0; mt < 2; mt++) {
                    mma16816(acc[mt][nt], ah[mt], b0h, b1h);
                    mma16816(acc[mt][nt], ah[mt], b0l, b1l);
                    mma16816(acc[mt][nt], al[mt], b0h, b1h);
                }
            }
        }
        __syncthreads();
        if (ch + 2 < NCH) ISSUE_W(ch + 2, buf);
        CP_COMMIT();
    }

    // epilogue: bias + partial L2-norm + partial 9 prompt dots for this half
    #pragma unroll
    for (int mt = 0; mt < 2; mt++) {
        int row = wm * 32 + mt * 16 + g;
        #pragma unroll
        for (int nt = 0; nt < 8; nt++) {
            int col = wn * 64 + nt * 8 + tig * 2;
            float b0 = Sbi[col], b1 = Sbi[col + 1];
            *reinterpret_cast<float2*>(&ysm[row * Y_STR + col]) =
                make_float2(acc[mt][nt][0] + b0, acc[mt][nt][1] + b1);
            *reinterpret_cast<float2*>(&ysm[(row + 8) * Y_STR + col]) =
                make_float2(acc[mt][nt][2] + b0, acc[mt][nt][3] + b1);
        }
    }
    __syncthreads();
    for (int r8 = 0; r8 < 8; r8++) {
        int row = wid * 8 + r8;
        float v[10];
        #pragma unroll
        for (int j = 0; j < 10; j++) v[j] = 0.f;
        for (int cc = lane; cc < 256; cc += 32) {
            float y = ysm[row * Y_STR + cc];
            v[0] += y * y;
            #pragma unroll
            for (int n = 0; n < NE; n++) v[1 + n] += y * Psm[n * 256 + cc];
        }
        #pragma unroll
        for (int j = 0; j < 10; j++)
            #pragma unroll
            for (int off = 16; off; off >>= 1) v[j] += __shfl_xor_sync(0xffffffffu, v[j], off);
        if (lane == 0) {
            #pragma unroll
            for (int j = 0; j < 10; j++) red[row * 10 + j] = v[j];
        }
    }
    __syncthreads();

    if (tid < 64) {
        int s = s0 + tid;
        if (s < S_SP) {
            size_t base = ((((size_t)i * T_TOK + t) * 2 + half) * 10) * S_SP + s;
            #pragma unroll
            for (int j = 0; j < 10; j++)
                g_part[base + (size_t)j * S_SP] = red[tid * 10 + j];
        }
    }
#undef ISSUE_W
#undef LOAD_X
#undef STORE_A
}

// combine partials + softmax over s + mean over levels
__global__ void k_softmax_mean() {
    int tn = blockIdx.x;
    int t = tn / NE, n = tn % NE;
    int tid = threadIdx.x;
    float accm[3] = {0.f, 0.f, 0.f};
    for (int i = 0; i < NL; i++) {
        const float* p0 = g_part + ((((size_t)i * T_TOK + t) * 2 + 0) * 10) * S_SP;
        const float* p1 = g_part + ((((size_t)i * T_TOK + t) * 2 + 1) * 10) * S_SP;
        float x[3];
        float mx = -INFINITY;
        #pragma unroll
        for (int j = 0; j < 3; j++) {
            int s = tid + j * 256;
            if (s < S_SP) {
                float nsq = p0[s] + p1[s];
                float d = p0[(size_t)(1 + n) * S_SP + s] + p1[(size_t)(1 + n) * S_SP + s];
                x[j] = 100.f * d * rsqrtf(nsq);
            } else x[j] = -INFINITY;
            mx = fmaxf(mx, x[j]);
        }
        mx = blockMax256(mx);
        float lsum = 0.f;
        float e[3];
        #pragma unroll
        for (int j = 0; j < 3; j++) {
            int s = tid + j * 256;
            e[j] = (s < S_SP) ? expf(x[j] - mx) : 0.f;
            lsum += e[j];
        }
        float tot = blockSum256(lsum);
        float inv = 0.25f / tot;
        #pragma unroll
        for (int j = 0; j < 3; j++) accm[j] += e[j] * inv;
    }
    float psum = 0.f;
    size_t obase = ((size_t)t * NE + n) * S_SP;
    #pragma unroll
    for (int j = 0; j < 3; j++) {
        int s = tid + j * 256;
        if (s < S_SP) {
            g_meanatt[obase + s] = accm[j];
            psum += accm[j];
        }
    }
    float tot = blockSum256(psum);
    if (tid == 0) g_pes[t * NE + n] = tot / (float)S_SP;
}

__global__ void k_tail(const float* __restrict__ ov,
                       const float* __restrict__ qw, const float* __restrict__ qb,
                       const float* __restrict__ kw, const float* __restrict__ kb,
                       float* __restrict__ out) {
    extern __shared__ float S[];
    float* matt = S;
    float* sp   = S + 736;
    float* qkb  = S + 740;
    float* pmx  = S + 744;
    float* toks = S + 752;
    float* Qs   = toks + 4608;
    float* KQs  = Qs + 2048;
    float* law  = KQs + 4608;

    int t = blockIdx.x, tid = threadIdx.x;
    int wid = tid >> 5, lane = tid & 31;

    float bsum[4] = {0.f, 0.f, 0.f, 0.f};
    for (int s = tid; s < S_SP; s += 256) {
        float m = -INFINITY;
        #pragma unroll
        for (int n = 0; n < NE; n++)
            m = fmaxf(m, g_meanatt[((size_t)t * NE + n) * S_SP + s]);
        matt[s] = m;
        int r = s / 27, c = s - r * 27;
        bool r0 = r < 14, r1 = r >= 13, c0 = c < 14, c1 = c >= 13;
        if (r0 && c0) bsum[0] += m;
        if (r0 && c1) bsum[1] += m;
        if (r1 && c0) bsum[2] += m;
        if (r1 && c1) bsum[3] += m;
    }
    #pragma unroll
    for (int q = 0; q < 4; q++) {
        float tot = blockSum256(bsum[q]);
        if (tid == 0) sp[q] = tot / 196.f;
    }
    if (tid == 0) {
        float pm = -INFINITY;
        for (int n = 0; n < NE; n++) pm = fmaxf(pm, g_pes[t * NE + n]);
        pmx[0] = pm;
    }
    __syncthreads();
    if (tid < 4) g_gsig[t * 4 + tid] = sp[tid] * pmx[0];

    {
        int nh = (tid < 128) ? 5 : 4;
        float accT[5][4];
        #pragma unroll
        for (int j = 0; j < 5; j++)
            #pragma unroll
            for (int q = 0; q < 4; q++) accT[j][q] = 0.f;
        const float* obase = ov + ((size_t)t * S_SP) * H_DIM + tid;
        for (int s = 0; s < S_SP; s++) {
            float a = matt[s];
            int r = s / 27, c = s - r * 27;
            float w0 = (r < 14 && c < 14) ? a : 0.f;
            float w1 = (r < 14 && c >= 13) ? a : 0.f;
            float w2 = (r >= 13 && c < 14) ? a : 0.f;
            float w3 = (r >= 13 && c >= 13) ? a : 0.f;
            const float* p = obase + (size_t)s * H_DIM;
            #pragma unroll
            for (int j = 0; j < 5; j++) {
                if (j < nh) {
                    float v = p[j * 256];
                    accT[j][0] += v * w0;
                    accT[j][1] += v * w1;
                    accT[j][2] += v * w2;
                    accT[j][3] += v * w3;
                }
            }
        }
        for (int j = 0; j < nh; j++) {
            int h = tid + j * 256;
            #pragma unroll
            for (int q = 0; q < 4; q++)
                toks[q * H_DIM + h] = (accT[j][q] * (1.f / 196.f)) / (sp[q] + 1e-8f);
        }
    }
    __syncthreads();

    for (int o = wid; o < E_DIM; o += 8) {
        float acc[4] = {0.f, 0.f, 0.f, 0.f};
        const float* wr = qw + (size_t)o * H_DIM;
        for (int k = lane; k < H_DIM; k += 32) {
            float w = wr[k];
            #pragma unroll
            for (int q = 0; q < 4; q++) acc[q] += w * toks[q * H_DIM + k];
        }
        #pragma unroll
        for (int off = 16; off; off >>= 1)
            #pragma unroll
            for (int q = 0; q < 4; q++) acc[q] += __shfl_xor_sync(0xffffffffu, acc[q], off);
        if (lane == 0) {
            float bv = qb[o];
            #pragma unroll
            for (int q = 0; q < 4; q++) Qs[q * E_DIM + o] = acc[q] + bv;
        }
    }
    __syncthreads();
    if (wid < 4) {
        float acc = 0.f;
        for (int e = lane; e < E_DIM; e += 32) acc += Qs[wid * E_DIM + e] * kb[e];
        #pragma unroll
        for (int off = 16; off; off >>= 1) acc += __shfl_xor_sync(0xffffffffu, acc, off);
        if (lane == 0) qkb[wid] = acc;
    }
    __syncthreads();

    {
        float a[5][4];
        #pragma unroll
        for (int j = 0; j < 5; j++)
            #pragma unroll
            for (int q = 0; q < 4; q++) a[j][q] = 0.f;
        for (int e = 0; e < E_DIM; e++) {
            float q0 = Qs[e], q1 = Qs[512 + e], q2 = Qs[1024 + e], q3 = Qs[1536 + e];
            const float* kr = kw + (size_t)e * H_DIM;
            #pragma unroll
            for (int j = 0; j < 5; j++) {
                int h = j * 256 + tid;
                if (h < H_DIM) {
                    float kv = kr[h];
                    a[j][0] += kv * q0; a[j][1] += kv * q1;
                    a[j][2] += kv * q2; a[j][3] += kv * q3;
                }
            }
        }
        #pragma unroll
        for (int j = 0; j < 5; j++) {
            int h = j * 256 + tid;
            if (h < H_DIM) {
                #pragma unroll
                for (int q = 0; q < 4; q++) KQs[q * H_DIM + h] = a[j][q];
            }
        }
    }
    __syncthreads();

    const float RS = 0.04419417382415922f;
    for (int s = wid; s < S_SP; s += 8) {
        float acc[4] = {0.f, 0.f, 0.f, 0.f};
        const float* orow = ov + ((size_t)t * S_SP + s) * H_DIM;
        for (int h = lane; h < H_DIM; h += 32) {
            float vv = orow[h];
            #pragma unroll
            for (int q = 0; q < 4; q++) acc[q] += vv * KQs[q * H_DIM + h];
        }
        #pragma unroll
        for (int off = 16; off; off >>= 1)
            #pragma unroll
            for (int q = 0; q < 4; q++) acc[q] += __shfl_xor_sync(0xffffffffu, acc[q], off);
        if (lane == 0) {
            #pragma unroll
            for (int q = 0; q < 4; q++) law[q * S_SP + s] = (acc[q] + qkb[q]) * RS;
        }
    }
    __syncthreads();
    for (int q = 0; q < 4; q++) {
        float mx = -INFINITY;
        for (int s = tid; s < S_SP; s += 256) mx = fmaxf(mx, law[q * S_SP + s]);
        mx = blockMax256(mx);
        float lsum = 0.f;
        for (int s = tid; s < S_SP; s += 256) {
            float e = expf(law[q * S_SP + s] - mx);
            law[q * S_SP + s] = e;
            lsum += e;
        }
        float tot = blockSum256(lsum);
        float inv = 1.f / tot;
        for (int s = tid; s < S_SP; s += 256) law[q * S_SP + s] *= inv;
        __syncthreads();
    }

    {
        int nh = (tid < 128) ? 5 : 4;
        float macc[5][4];
        #pragma unroll
        for (int j = 0; j < 5; j++)
            #pragma unroll
            for (int q = 0; q < 4; q++) macc[j][q] = 0.f;
        const float* obase = ov + ((size_t)t * S_SP) * H_DIM + tid;
        for (int s = 0; s < S_SP; s++) {
            float a0 = law[0 * S_SP + s], a1 = law[1 * S_SP + s];
            float a2 = law[2 * S_SP + s], a3 = law[3 * S_SP + s];
            const float* p = obase + (size_t)s * H_DIM;
            #pragma unroll
            for (int j = 0; j < 5; j++) {
                if (j < nh) {
                    float v = p[j * 256];
                    macc[j][0] += a0 * v;
                    macc[j][1] += a1 * v;
                    macc[j][2] += a2 * v;
                    macc[j][3] += a3 * v;
                }
            }
        }
        for (int j = 0; j < nh; j++) {
            int h = tid + j * 256;
            #pragma unroll
            for (int q = 0; q < 4; q++)
                out[OUT_MAJOR + ((size_t)t * 4 + q) * H_DIM + h] = macc[j][q];
        }
    }
}

__global__ void k_finpred(const float* __restrict__ w1, const float* __restrict__ b1,
                          const float* __restrict__ w2, const float* __restrict__ b2,
                          float* __restrict__ out) {
    int b = blockIdx.x, tid = threadIdx.x;
    __shared__ float gsh[32];
    __shared__ float gsum_sh;
    __shared__ float fr[H_DIM];
    __shared__ float hid[E_DIM];
    __shared__ float lg[NE];
    if (tid < 32) {
        int p = tid >> 2, q = tid & 3;
        gsh[tid] = g_gsig[(b * P_PAT + p) * 4 + q];
    }
    __syncthreads();
    if (tid == 0) {
        float s = 0.f;
        for (int i = 0; i < 32; i++) s += gsh[i];
        gsum_sh = s;
    }
    __syncthreads();
    float denom = gsum_sh / 32.f + 1e-8f;
    int nh = (tid < 128) ? 5 : 4;
    for (int j = 0; j < nh; j++) {
        int h = tid + j * 256;
        float acc = 0.f;
        for (int idx = 0; idx < 32; idx++) {
            int p = idx >> 2, q = idx & 3;
            acc += out[OUT_MAJOR + ((size_t)(b * P_PAT + p) * 4 + q) * H_DIM + h] * gsh[idx];
        }
        float fin = (acc / 32.f) / denom;
        fr[h] = fin;
        out[OUT_FINAL + (size_t)b * H_DIM + h] = fin;
    }
    __syncthreads();
    int wid = tid >> 5, lane = tid & 31;
    for (int o = wid; o < E_DIM; o += 8) {
        float acc = 0.f;
        const float* wr = w1 + (size_t)o * H_DIM;
        for (int k = lane; k < H_DIM; k += 32) acc += wr[k] * fr[k];
        #pragma unroll
        for (int off = 16; off; off >>= 1) acc += __shfl_xor_sync(0xffffffffu, acc, off);
        if (lane == 0) hid[o] = gelu_exact(acc + b1[o]);
    }
    __syncthreads();
    for (int n = 0; n < NE; n++) {
        float v = hid[tid] * w2[n * E_DIM + tid] + hid[tid + 256] * w2[n * E_DIM + tid + 256];
        float tot = blockSum256(v);
        if (tid == 0) lg[n] = tot + b2[n];
    }
    __syncthreads();
    if (tid == 0) {
        float mx = -INFINITY;
        for (int n = 0; n < NE; n++) mx = fmaxf(mx, lg[n]);
        float sum = 0.f;
        float e[NE];
        for (int n = 0; n < NE; n++) { e[n] = expf(lg[n] - mx); sum += e[n]; }
        for (int n = 0; n < NE; n++) out[OUT_PREDS + b * NE + n] = e[n] / sum;
    }
}

extern "C" void kernel_launch(void* const* d_in, const int* in_sizes, int n_in,
                              void* d_out, int out_size) {
    const float* ov      = (const float*)d_in[0];
    const float* sig     = (const float*)d_in[1];
    const float* emo     = (const float*)d_in[2];
    const float* pool_w  = (const float*)d_in[3];
    const float* pool_b  = (const float*)d_in[4];
    const float* cls_w1  = (const float*)d_in[5];
    const float* cls_b1  = (const float*)d_in[6];
    const float* cls_w2  = (const float*)d_in[7];
    const float* cls_b2  = (const float*)d_in[8];
    const float* sig_w   = (const float*)d_in[9];
    const float* sig_b   = (const float*)d_in[10];
    const float* prm_w   = (const float*)d_in[11];
    const float* prm_b   = (const float*)d_in[12];
    const float* pred_w1 = (const float*)d_in[13];
    const float* pred_b1 = (const float*)d_in[14];
    const float* pred_w2 = (const float*)d_in[15];
    const float* pred_b2 = (const float*)d_in[16];
    const float* q_w     = (const float*)d_in[17];
    const float* q_b     = (const float*)d_in[18];
    const float* k_w     = (const float*)d_in[19];
    const float* k_b     = (const float*)d_in[20];
    float* out = (float*)d_out;

    cudaFuncSetAttribute(k_sig_mma, cudaFuncAttributeMaxDynamicSharedMemorySize, SM2_TOTAL);
    cudaFuncSetAttribute(k_tail, cudaFuncAttributeMaxDynamicSharedMemorySize, 61440);

    k_wsplit<<<1024, 256>>>(sig_w);
    k_pool<<<dim3(B_IMG, 9), 128>>>(ov, pool_w);
    k_cls1<<<64, 256>>>(cls_w1, cls_b1, pool_b);
    k_cls2<<<64, 256>>>(cls_w2, cls_b2);
    k_puv<<<dim3(16, NL), 256>>>(emo, prm_w);
    k_prompts2<<<dim3(NE, B_IMG, NL), 256>>>(prm_b);
    k_sig_mma<<<dim3(12, T_TOK, NL * 2), 256, SM2_TOTAL>>>(sig, sig_b);
    k_softmax_mean<<<T_TOK * NE, 256>>>();
    k_tail<<<T_TOK, 256, 61440>>>(ov, q_w, q_b, k_w, k_b, out);
    k_finpred<<<B_IMG, 256>>>(pred_w1, pred_b1, pred_w2, pred_b2, out);
}